// round 11
// baseline (speedup 1.0000x reference)
#include <cuda_runtime.h>
#include <cuda_bf16.h>

// ---------------------------------------------------------------------------
// graph_encoder: B=16, N=1024, H=256, 4 heads (d=64), 2 layers.
// R10: pre-interleaved weights (pure cp.async B tiles), k32 GEMM stages,
//      pre-packed V for flash (pure cp.async V tiles).
// ---------------------------------------------------------------------------

#define Bsz   16
#define Nn    1024
#define Hd    256
#define Ee    767
#define Rr    256
#define ROOTI 46
#define Mrows (Bsz * Nn)
#define XSZ   (Mrows * Hd)
#define H1SZ  (Mrows * 4 * Hd)
#define QKVSZ (Mrows * 3 * Hd)

__device__ float          g_x  [XSZ];
__device__ __nv_bfloat16  g_xb [XSZ];
__device__ __nv_bfloat16  g_qkvb[QKVSZ];
__device__ float          g_o  [XSZ];
__device__ float          g_t  [XSZ];
__device__ __nv_bfloat16  g_tb [XSZ];
__device__ float          g_h2 [XSZ];
__device__ __nv_bfloat16  g_h1b[H1SZ];
__device__ unsigned       g_wqkvi[2 * 128 * 768];    // interleaved k-pair words
__device__ unsigned       g_w1i  [2 * 128 * 1024];
__device__ unsigned       g_w2i  [2 * 512 * 256];
__device__ unsigned       g_vp   [Bsz * 4 * 512 * 64]; // V j-pair words
__device__ unsigned       g_adjb[Bsz * Nn * 32];

// ---------------------------------------------------------------------------
__device__ __forceinline__ unsigned packbf(float lo, float hi)
{
    unsigned u;
    asm("cvt.rn.bf16x2.f32 %0, %1, %2;" : "=r"(u) : "f"(hi), "f"(lo));
    return u;
}
__device__ __forceinline__ unsigned prmt(unsigned a, unsigned b, unsigned s)
{
    unsigned r;
    asm("prmt.b32 %0, %1, %2, %3;" : "=r"(r) : "r"(a), "r"(b), "r"(s));
    return r;
}
__device__ __forceinline__ void cpasync16(unsigned dst, const void* src)
{
    asm volatile("cp.async.cg.shared.global [%0], [%1], 16;\n"
                 :: "r"(dst), "l"(src));
}
#define CP_COMMIT asm volatile("cp.async.commit_group;\n" ::: "memory")
#define CP_WAIT0  asm volatile("cp.async.wait_group 0;\n" ::: "memory")

#define BF16_MMA(d, a, b)                                                     \
    asm volatile(                                                             \
        "mma.sync.aligned.m16n8k16.row.col.f32.bf16.bf16.f32 "                \
        "{%0,%1,%2,%3},{%4,%5,%6,%7},{%8,%9},{%0,%1,%2,%3};"                  \
        : "+f"((d)[0]), "+f"((d)[1]), "+f"((d)[2]), "+f"((d)[3])              \
        : "r"((a)[0]), "r"((a)[1]), "r"((a)[2]), "r"((a)[3]),                 \
          "r"((b)[0]), "r"((b)[1]))

// ---------------------------------------------------------------------------
__global__ void embed_kernel(const int* __restrict__ ents,
                             const int* __restrict__ rels,
                             const float* __restrict__ ent_table,
                             const float* __restrict__ rel_table,
                             float* __restrict__ x,
                             __nv_bfloat16* __restrict__ xb)
{
    int bn = blockIdx.x;
    int b  = bn >> 10;
    int n  = bn & 1023;
    const float* src;
    if (n < Ee)            src = ent_table + (size_t)ents[b * Ee + n] * Hd;
    else if (n < Ee + Rr)  src = rel_table + (size_t)rels[b * Rr + (n - Ee)] * Hd;
    else                   src = rel_table + (size_t)ROOTI * Hd;
    float v = src[threadIdx.x];
    size_t idx = (size_t)bn * Hd + threadIdx.x;
    x[idx]  = v;
    xb[idx] = __float2bfloat16(v);
}

// ---------------------------------------------------------------------------
// Weight interleave: out[kw*768 + c] = bf16x2(W[2kw][c], W[2kw+1][c]), qkv-fused
// ---------------------------------------------------------------------------
__global__ void packqkv_i(const float* __restrict__ wq,
                          const float* __restrict__ wk,
                          const float* __restrict__ wv,
                          unsigned* __restrict__ out)
{
    int j = blockIdx.y;
    int i = blockIdx.x * 256 + threadIdx.x;        // 0..98303
    int kw = i / 768, c = i - kw * 768;
    const float* base;
    int cc;
    if (c < 256)      { base = wq; cc = c; }
    else if (c < 512) { base = wk; cc = c - 256; }
    else              { base = wv; cc = c - 512; }
    base += (size_t)j * 65536;
    out[(size_t)j * 98304 + i] =
        packbf(base[(2 * kw) * 256 + cc], base[(2 * kw + 1) * 256 + cc]);
}

// Generic interleave: in [K,N] fp32 -> out [K/2][N] words
__global__ void cvt_i(const float* __restrict__ in, unsigned* __restrict__ out,
                      int N, int wordsPerLayer)
{
    int j = blockIdx.y;
    int i = blockIdx.x * 256 + threadIdx.x;        // word index in layer
    int kw = i / N, n = i - kw * N;
    const float* src = in + (size_t)j * 2 * wordsPerLayer;
    out[(size_t)j * wordsPerLayer + i] =
        packbf(src[(size_t)(2 * kw) * N + n], src[(size_t)(2 * kw + 1) * N + n]);
}

// ---------------------------------------------------------------------------
// V pre-pack: vp[((b*4+h)*512 + jw)*64 + d] = bf16x2(V[b][2jw][h*64+d], row+1)
// Each thread handles 2 consecutive d (one 32-bit src word per row).
// ---------------------------------------------------------------------------
__global__ void vpack_kernel(const __nv_bfloat16* __restrict__ qkv,
                             unsigned* __restrict__ vp)
{
    int idx = blockIdx.x * 256 + threadIdx.x;      // 0..2^20-1
    int wi  = idx * 2;
    int d   = wi & 63;
    int jw  = (wi >> 6) & 511;
    int h   = (wi >> 15) & 3;
    int b   = wi >> 17;
    const __nv_bfloat16* r0 = qkv + (size_t)(b * 1024 + 2 * jw) * 768
                            + 512 + h * 64 + d;
    unsigned w0 = *(const unsigned*)r0;
    unsigned w1 = *(const unsigned*)(r0 + 768);
    vp[wi]     = prmt(w0, w1, 0x5410);
    vp[wi + 1] = prmt(w0, w1, 0x7632);
}

// ---------------------------------------------------------------------------
__global__ void adjpack_kernel(const int* __restrict__ adj,
                               unsigned* __restrict__ adjb)
{
    int gw   = blockIdx.x * 8 + (threadIdx.x >> 5);
    int lane = threadIdx.x & 31;
    int row  = gw >> 5;
    int wrd  = gw & 31;
    int v = adj[((size_t)row << 10) + wrd * 32 + lane];
    unsigned m = __ballot_sync(0xffffffffu, v != 0);
    if (lane == 0) adjb[gw] = m;
}

// ---------------------------------------------------------------------------
// bf16 GEMM: 128x128 block, 8 warps (2x4), warp 64x32, k32 stages.
// A bf16 [m][k] via cp.async -> smem [m][20 words]. W interleaved words
// [kw][Nc] via cp.async -> smem [kw 0..15][136]. All frag loads conflict-free.
// ---------------------------------------------------------------------------
#define ASTR 20
#define ASTG (128 * ASTR)          // 2560 words
#define BSTG (16 * 136)            // 2176 words
#define BOFF (2 * ASTG)

__global__ void __launch_bounds__(256, 2)
gemm_tc(const __nv_bfloat16* __restrict__ A,
        const unsigned* __restrict__ Wt,
        float* __restrict__ Cf,
        __nv_bfloat16* __restrict__ Cb,
        int K, int lda, int Nc, int ldc,
        const float* __restrict__ bias,
        const float* __restrict__ alpha,
        int mode)
{
    __shared__ __align__(16) unsigned sm[2 * ASTG + 2 * BSTG];
    unsigned sbase = (unsigned)__cvta_generic_to_shared(sm);

    int t    = threadIdx.x;
    int w    = t >> 5, lane = t & 31;
    int gid  = lane >> 2, tid4 = lane & 3;
    int wm0  = (w >> 2) * 64;
    int wn0  = (w & 3) * 32;
    int row0 = blockIdx.y << 7;
    int col0 = blockIdx.x << 7;

    int arow = t >> 1;             // 0..127
    int akw  = (t & 1) * 8;        // A word offset 0/8 (16 k elems)
    int bkw  = t >> 4;             // 0..15
    int bn8  = (t & 15) * 8;       // 8 n-words

    const __nv_bfloat16* Ap = A + (size_t)(row0 + arow) * lda + akw * 2;
    const unsigned*      Bp = Wt + (size_t)bkw * Nc + col0 + bn8;

    unsigned aDst = sbase + (arow * ASTR + akw) * 4;
    unsigned bDst = sbase + (BOFF + bkw * 136 + bn8) * 4;

    // preload stage 0
    cpasync16(aDst, Ap);           cpasync16(aDst + 16, Ap + 8);
    cpasync16(bDst, Bp);           cpasync16(bDst + 16, Bp + 4);
    CP_COMMIT;
    CP_WAIT0;
    __syncthreads();

    float acc[4][4][4] = {};
    int buf = 0;
    int nst = K >> 5;

    for (int s = 0; s < nst; s++) {
        if (s + 1 < nst) {
            const __nv_bfloat16* An = Ap + (s + 1) * 32;
            const unsigned*      Bn = Bp + (size_t)(s + 1) * 16 * Nc;
            unsigned ad = aDst + (buf ^ 1) * (ASTG * 4);
            unsigned bd = bDst + (buf ^ 1) * (BSTG * 4);
            cpasync16(ad, An);      cpasync16(ad + 16, An + 8);
            cpasync16(bd, Bn);      cpasync16(bd + 16, Bn + 4);
            CP_COMMIT;
        }
        const unsigned* Ab = sm + buf * ASTG;
        const unsigned* Bb = sm + BOFF + buf * BSTG;
#pragma unroll
        for (int hh = 0; hh < 2; hh++) {
            unsigned af[4][4], bfr[4][2];
#pragma unroll
            for (int nt = 0; nt < 4; nt++) {
                bfr[nt][0] = Bb[(hh * 8 + tid4) * 136 + wn0 + nt * 8 + gid];
                bfr[nt][1] = Bb[(hh * 8 + tid4 + 4) * 136 + wn0 + nt * 8 + gid];
            }
#pragma unroll
            for (int mt = 0; mt < 4; mt++) {
                int r = (wm0 + mt * 16 + gid) * ASTR + hh * 8;
                af[mt][0] = Ab[r + tid4];
                af[mt][1] = Ab[r + 8 * ASTR + tid4];
                af[mt][2] = Ab[r + tid4 + 4];
                af[mt][3] = Ab[r + 8 * ASTR + tid4 + 4];
            }
#pragma unroll
            for (int mt = 0; mt < 4; mt++)
#pragma unroll
                for (int nt = 0; nt < 4; nt++)
                    BF16_MMA(acc[mt][nt], af[mt], bfr[nt]);
        }
        if (s + 1 < nst) {
            CP_WAIT0;
            __syncthreads();
            buf ^= 1;
        }
    }

#pragma unroll
    for (int mt = 0; mt < 4; mt++) {
        int r0 = row0 + wm0 + mt * 16 + gid;
#pragma unroll
        for (int nt = 0; nt < 4; nt++) {
            int c = col0 + wn0 + nt * 8 + 2 * tid4;
            float v0 = acc[mt][nt][0], v1 = acc[mt][nt][1];
            float v2 = acc[mt][nt][2], v3 = acc[mt][nt][3];
            if (mode != 0) {
                float b0v = bias[c], b1v = bias[c + 1];
                v0 += b0v; v1 += b1v; v2 += b0v; v3 += b1v;
            }
            if (mode == 1) {
                float a0v = alpha[c], a1v = alpha[c + 1];
                v0 = v0 >= 0.f ? v0 : a0v * v0;
                v1 = v1 >= 0.f ? v1 : a1v * v1;
                v2 = v2 >= 0.f ? v2 : a0v * v2;
                v3 = v3 >= 0.f ? v3 : a1v * v3;
            }
            if (Cf) {
                *(float2*)&Cf[(size_t)r0 * ldc + c]       = make_float2(v0, v1);
                *(float2*)&Cf[(size_t)(r0 + 8) * ldc + c] = make_float2(v2, v3);
            } else {
                *(unsigned*)&Cb[(size_t)r0 * ldc + c]       = packbf(v0, v1);
                *(unsigned*)&Cb[(size_t)(r0 + 8) * ldc + c] = packbf(v2, v3);
            }
        }
    }
}

// ---------------------------------------------------------------------------
// Fused flash attention. Q/K [row][36 words] cp.async; V [jw][72] cp.async
// from pre-packed vp; P [cw][136]. All fragment loads conflict-free.
// ---------------------------------------------------------------------------
#define FL_QS   0
#define FL_KS   4608                 // 128*36
#define FL_VS   (FL_KS + 4608)
#define FL_PS   (FL_VS + 64 * 72)
#define FL_RED  (FL_PS + 64 * 136)
#define FL_SMEM ((FL_RED + 2 * 4 * 128) * 4)

__global__ void __launch_bounds__(256, 2)
flash_attn(const __nv_bfloat16* __restrict__ qkv,
           const unsigned* __restrict__ vp,
           const unsigned* __restrict__ adjb,
           const float* __restrict__ X,
           float* __restrict__ O)
{
    extern __shared__ __align__(16) unsigned sm[];
    unsigned sbase = (unsigned)__cvta_generic_to_shared(sm);
    unsigned* Qs = sm + FL_QS;
    unsigned* Ks = sm + FL_KS;
    unsigned* Vs = sm + FL_VS;
    unsigned* Ps = sm + FL_PS;
    float* redm = (float*)(sm + FL_RED);
    float* reds = redm + 4 * 128;

    int t = threadIdx.x;
    int w = t >> 5, lane = t & 31;
    int gid = lane >> 2, tid4 = lane & 3;
    int wm0 = (w >> 2) * 64;
    int wn0 = (w & 3) * 32;
    int wd0 = (w & 3) * 16;
    int z = blockIdx.y;
    int b = z >> 2, h = z & 3;
    int i0 = blockIdx.x << 7;

    int cprow = t >> 1;
    int cpw0  = (t & 1) * 16;

    // ---- Q tile (cp.async), once ----
    {
        const __nv_bfloat16* src = qkv + (size_t)(b * Nn + i0 + cprow) * 768
                                 + h * 64 + cpw0 * 2;
        unsigned dst = sbase + (FL_QS + cprow * 36 + cpw0) * 4;
        cpasync16(dst,      src);
        cpasync16(dst + 16, src + 8);
        cpasync16(dst + 32, src + 16);
        cpasync16(dst + 48, src + 24);
        CP_COMMIT;
    }

    float m_st[8], l_st[8];
    float oac[4][2][4] = {};
#pragma unroll
    for (int s = 0; s < 8; s++) { m_st[s] = -1e4f; l_st[s] = 0.f; }

    for (int jt = 0; jt < 8; jt++) {
        int j0 = jt << 7;
        __syncthreads();

        // ---- K tile (cp.async) ----
        {
            const __nv_bfloat16* src = qkv + (size_t)(b * Nn + j0 + cprow) * 768
                                     + 256 + h * 64 + cpw0 * 2;
            unsigned dst = sbase + (FL_KS + cprow * 36 + cpw0) * 4;
            cpasync16(dst,      src);
            cpasync16(dst + 16, src + 8);
            cpasync16(dst + 32, src + 16);
            cpasync16(dst + 48, src + 24);
        }
        // ---- V tile (cp.async from prepacked vp) ----
        {
            int jw = t >> 2;
            int qo = (t & 3) * 16;
            const unsigned* src = vp + ((size_t)z * 512 + jt * 64 + jw) * 64 + qo;
            unsigned dst = sbase + (FL_VS + jw * 72 + qo) * 4;
            cpasync16(dst,      src);
            cpasync16(dst + 16, src + 4);
            cpasync16(dst + 32, src + 8);
            cpasync16(dst + 48, src + 12);
        }
        CP_COMMIT;
        CP_WAIT0;
        __syncthreads();

        // ---- S = Q @ K^T (128x128, d=64 -> 32 words) ----
        float sac[4][4][4] = {};
#pragma unroll
        for (int kc = 0; kc < 32; kc += 8) {
            unsigned af[4][4], bfr[4][2];
#pragma unroll
            for (int nt = 0; nt < 4; nt++) {
                int jr = (wn0 + nt * 8 + gid) * 36;
                bfr[nt][0] = Ks[jr + kc + tid4];
                bfr[nt][1] = Ks[jr + kc + tid4 + 4];
            }
#pragma unroll
            for (int mt = 0; mt < 4; mt++) {
                int r = (wm0 + mt * 16 + gid) * 36;
                af[mt][0] = Qs[r + kc + tid4];
                af[mt][1] = Qs[r + 288 + kc + tid4];
                af[mt][2] = Qs[r + kc + tid4 + 4];
                af[mt][3] = Qs[r + 288 + kc + tid4 + 4];
            }
#pragma unroll
            for (int mt = 0; mt < 4; mt++)
#pragma unroll
                for (int nt = 0; nt < 4; nt++)
                    BF16_MMA(sac[mt][nt], af[mt], bfr[nt]);
        }

        // ---- mask + scale, per-row tile max ----
        int wq = (j0 + wn0) >> 5;
        float tmax[8];
#pragma unroll
        for (int s = 0; s < 8; s++) tmax[s] = -1e30f;
#pragma unroll
        for (int mt = 0; mt < 4; mt++) {
            int r = i0 + wm0 + mt * 16 + gid;
            unsigned w0 = adjb[(((size_t)(b * Nn + r)) << 5) + wq];
            unsigned w1 = adjb[(((size_t)(b * Nn + r + 8)) << 5) + wq];
#pragma unroll
            for (int nt = 0; nt < 4; nt++) {
                int bit = nt * 8 + 2 * tid4;
                sac[mt][nt][0] = (w0 >> bit) & 1       ? sac[mt][nt][0] * 0.0625f : -1e30f;
                sac[mt][nt][1] = (w0 >> (bit + 1)) & 1 ? sac[mt][nt][1] * 0.0625f : -1e30f;
                sac[mt][nt][2] = (w1 >> bit) & 1       ? sac[mt][nt][2] * 0.0625f : -1e30f;
                sac[mt][nt][3] = (w1 >> (bit + 1)) & 1 ? sac[mt][nt][3] * 0.0625f : -1e30f;
                tmax[mt * 2 + 0] = fmaxf(tmax[mt * 2 + 0],
                                         fmaxf(sac[mt][nt][0], sac[mt][nt][1]));
                tmax[mt * 2 + 1] = fmaxf(tmax[mt * 2 + 1],
                                         fmaxf(sac[mt][nt][2], sac[mt][nt][3]));
            }
        }
#pragma unroll
        for (int s = 0; s < 8; s++) {
            tmax[s] = fmaxf(tmax[s], __shfl_xor_sync(0xffffffffu, tmax[s], 1));
            tmax[s] = fmaxf(tmax[s], __shfl_xor_sync(0xffffffffu, tmax[s], 2));
        }
        if (tid4 == 0) {
#pragma unroll
            for (int mt = 0; mt < 4; mt++) {
                redm[(w & 3) * 128 + wm0 + mt * 16 + gid]     = tmax[mt * 2];
                redm[(w & 3) * 128 + wm0 + mt * 16 + gid + 8] = tmax[mt * 2 + 1];
            }
        }
        __syncthreads();

        float alp[8];
#pragma unroll
        for (int mt = 0; mt < 4; mt++)
#pragma unroll
            for (int q = 0; q < 2; q++) {
                int r = wm0 + mt * 16 + gid + q * 8;
                float tm = fmaxf(fmaxf(redm[r], redm[128 + r]),
                                 fmaxf(redm[256 + r], redm[384 + r]));
                int s = mt * 2 + q;
                float mn = fmaxf(m_st[s], fmaxf(tm, -1e4f));
                alp[s] = __expf(m_st[s] - mn);
                m_st[s] = mn;
            }

        // ---- exp, partial sums, store P (bf16 pairs along j) ----
        float psum[8] = {};
#pragma unroll
        for (int mt = 0; mt < 4; mt++) {
            int r = wm0 + mt * 16 + gid;
            int s0 = mt * 2, s1 = mt * 2 + 1;
#pragma unroll
            for (int nt = 0; nt < 4; nt++) {
                int cw = (wn0 >> 1) + nt * 4 + tid4;
                float e0 = __expf(sac[mt][nt][0] - m_st[s0]);
                float e1 = __expf(sac[mt][nt][1] - m_st[s0]);
                float e2 = __expf(sac[mt][nt][2] - m_st[s1]);
                float e3 = __expf(sac[mt][nt][3] - m_st[s1]);
                psum[s0] += e0 + e1;
                psum[s1] += e2 + e3;
                Ps[cw * 136 + r]     = packbf(e0, e1);
                Ps[cw * 136 + r + 8] = packbf(e2, e3);
            }
        }
#pragma unroll
        for (int s = 0; s < 8; s++) {
            psum[s] += __shfl_xor_sync(0xffffffffu, psum[s], 1);
            psum[s] += __shfl_xor_sync(0xffffffffu, psum[s], 2);
        }
        if (tid4 == 0) {
#pragma unroll
            for (int mt = 0; mt < 4; mt++) {
                reds[(w & 3) * 128 + wm0 + mt * 16 + gid]     = psum[mt * 2];
                reds[(w & 3) * 128 + wm0 + mt * 16 + gid + 8] = psum[mt * 2 + 1];
            }
        }
        __syncthreads();

        // ---- update l, rescale O ----
#pragma unroll
        for (int mt = 0; mt < 4; mt++)
#pragma unroll
            for (int q = 0; q < 2; q++) {
                int r = wm0 + mt * 16 + gid + q * 8;
                int s = mt * 2 + q;
                float ps = reds[r] + reds[128 + r] + reds[256 + r] + reds[384 + r];
                l_st[s] = l_st[s] * alp[s] + ps;
            }
#pragma unroll
        for (int mt = 0; mt < 4; mt++)
#pragma unroll
            for (int nt = 0; nt < 2; nt++) {
                oac[mt][nt][0] *= alp[mt * 2];
                oac[mt][nt][1] *= alp[mt * 2];
                oac[mt][nt][2] *= alp[mt * 2 + 1];
                oac[mt][nt][3] *= alp[mt * 2 + 1];
            }

        // ---- O += P @ V (128x64, k=128 -> 64 words) ----
#pragma unroll
        for (int ko = 0; ko < 64; ko += 8) {
            unsigned af[4][4], bfr[2][2];
#pragma unroll
            for (int nt = 0; nt < 2; nt++) {
                bfr[nt][0] = Vs[(ko + tid4) * 72 + wd0 + nt * 8 + gid];
                bfr[nt][1] = Vs[(ko + tid4 + 4) * 72 + wd0 + nt * 8 + gid];
            }
#pragma unroll
            for (int mt = 0; mt < 4; mt++) {
                af[mt][0] = Ps[(ko + tid4) * 136 + wm0 + mt * 16 + gid];
                af[mt][1] = Ps[(ko + tid4) * 136 + wm0 + mt * 16 + gid + 8];
                af[mt][2] = Ps[(ko + tid4 + 4) * 136 + wm0 + mt * 16 + gid];
                af[mt][3] = Ps[(ko + tid4 + 4) * 136 + wm0 + mt * 16 + gid + 8];
            }
#pragma unroll
            for (int mt = 0; mt < 4; mt++)
#pragma unroll
                for (int nt = 0; nt < 2; nt++)
                    BF16_MMA(oac[mt][nt], af[mt], bfr[nt]);
        }
    }

    // ---- epilogue: O/l + residual X ----
    float inv[8];
#pragma unroll
    for (int s = 0; s < 8; s++) inv[s] = 1.f / l_st[s];
#pragma unroll
    for (int mt = 0; mt < 4; mt++) {
        int r = i0 + wm0 + mt * 16 + gid;
#pragma unroll
        for (int nt = 0; nt < 2; nt++) {
            int c = wd0 + nt * 8 + 2 * tid4;
            size_t idx0 = (size_t)(b * Nn + r) * Hd + h * 64 + c;
            size_t idx1 = (size_t)(b * Nn + r + 8) * Hd + h * 64 + c;
            float2 x0 = *(const float2*)&X[idx0];
            float2 x1 = *(const float2*)&X[idx1];
            *(float2*)&O[idx0] = make_float2(oac[mt][nt][0] * inv[mt * 2] + x0.x,
                                             oac[mt][nt][1] * inv[mt * 2] + x0.y);
            *(float2*)&O[idx1] = make_float2(oac[mt][nt][2] * inv[mt * 2 + 1] + x1.x,
                                             oac[mt][nt][3] * inv[mt * 2 + 1] + x1.y);
        }
    }
}

// ---------------------------------------------------------------------------
__global__ void ln_kernel(const float* __restrict__ A,
                          const float* __restrict__ Badd,
                          const float* __restrict__ gamma,
                          const float* __restrict__ beta,
                          float* __restrict__ out,
                          __nv_bfloat16* __restrict__ outb)
{
    int row  = (blockIdx.x * blockDim.x + threadIdx.x) >> 5;
    int lane = threadIdx.x & 31;
    size_t base = (size_t)row * Hd + lane * 8;

    float4 v0 = *(const float4*)&A[base];
    float4 v1 = *(const float4*)&A[base + 4];
    if (Badd) {
        float4 b0 = *(const float4*)&Badd[base];
        float4 b1 = *(const float4*)&Badd[base + 4];
        v0.x += b0.x; v0.y += b0.y; v0.z += b0.z; v0.w += b0.w;
        v1.x += b1.x; v1.y += b1.y; v1.z += b1.z; v1.w += b1.w;
    }

    float s = v0.x + v0.y + v0.z + v0.w + v1.x + v1.y + v1.z + v1.w;
#pragma unroll
    for (int off = 16; off > 0; off >>= 1)
        s += __shfl_xor_sync(0xffffffffu, s, off);
    float mean = s * (1.f / Hd);

    float d0x = v0.x - mean, d0y = v0.y - mean, d0z = v0.z - mean, d0w = v0.w - mean;
    float d1x = v1.x - mean, d1y = v1.y - mean, d1z = v1.z - mean, d1w = v1.w - mean;
    float q = d0x * d0x + d0y * d0y + d0z * d0z + d0w * d0w
            + d1x * d1x + d1y * d1y + d1z * d1z + d1w * d1w;
#pragma unroll
    for (int off = 16; off > 0; off >>= 1)
        q += __shfl_xor_sync(0xffffffffu, q, off);
    float rstd = rsqrtf(q * (1.f / Hd) + 1e-5f);

    int c = lane * 8;
    float4 g0 = *(const float4*)&gamma[c];
    float4 g1 = *(const float4*)&gamma[c + 4];
    float4 b0 = *(const float4*)&beta[c];
    float4 b1 = *(const float4*)&beta[c + 4];
    float o0 = d0x * rstd * g0.x + b0.x;
    float o1 = d0y * rstd * g0.y + b0.y;
    float o2 = d0z * rstd * g0.z + b0.z;
    float o3 = d0w * rstd * g0.w + b0.w;
    float o4 = d1x * rstd * g1.x + b1.x;
    float o5 = d1y * rstd * g1.y + b1.y;
    float o6 = d1z * rstd * g1.z + b1.z;
    float o7 = d1w * rstd * g1.w + b1.w;
    *(float4*)&out[base]     = make_float4(o0, o1, o2, o3);
    *(float4*)&out[base + 4] = make_float4(o4, o5, o6, o7);
    if (outb) {
        *(uint4*)&outb[base] = make_uint4(packbf(o0, o1), packbf(o2, o3),
                                          packbf(o4, o5), packbf(o6, o7));
    }
}

// ---------------------------------------------------------------------------
__global__ void fill_tail_kernel(float* __restrict__ out, int start, int total)
{
    int i = blockIdx.x * blockDim.x + threadIdx.x + start;
    if (i < total) out[i] = 1.0f;
}

// ---------------------------------------------------------------------------
extern "C" void kernel_launch(void* const* d_in, const int* in_sizes, int n_in,
                              void* d_out, int out_size)
{
    const int*   ents      = (const int*)  d_in[0];
    const int*   rels      = (const int*)  d_in[1];
    const int*   adjs      = (const int*)  d_in[2];
    const float* ent_table = (const float*)d_in[3];
    const float* rel_table = (const float*)d_in[4];
    const float* Wq        = (const float*)d_in[5];
    const float* Wk        = (const float*)d_in[6];
    const float* Wv        = (const float*)d_in[7];
    const float* l1w       = (const float*)d_in[8];
    const float* l1b       = (const float*)d_in[9];
    const float* l2w       = (const float*)d_in[10];
    const float* l2b       = (const float*)d_in[11];
    const float* ln_g      = (const float*)d_in[12];
    const float* ln_b      = (const float*)d_in[13];
    const float* alpha     = (const float*)d_in[14];
    float* out = (float*)d_out;

    float *x, *o, *tb, *h2;
    __nv_bfloat16 *xb, *qkvb, *tbb, *h1b;
    unsigned *wqkvi, *w1i, *w2i, *vp, *adjb;
    cudaGetSymbolAddress((void**)&x,     g_x);
    cudaGetSymbolAddress((void**)&xb,    g_xb);
    cudaGetSymbolAddress((void**)&qkvb,  g_qkvb);
    cudaGetSymbolAddress((void**)&o,     g_o);
    cudaGetSymbolAddress((void**)&tb,    g_t);
    cudaGetSymbolAddress((void**)&tbb,   g_tb);
    cudaGetSymbolAddress((void**)&h2,    g_h2);
    cudaGetSymbolAddress((void**)&h1b,   g_h1b);
    cudaGetSymbolAddress((void**)&wqkvi, g_wqkvi);
    cudaGetSymbolAddress((void**)&w1i,   g_w1i);
    cudaGetSymbolAddress((void**)&w2i,   g_w2i);
    cudaGetSymbolAddress((void**)&vp,    g_vp);
    cudaGetSymbolAddress((void**)&adjb,  g_adjb);

    cudaFuncSetAttribute(flash_attn, cudaFuncAttributeMaxDynamicSharedMemorySize,
                         FL_SMEM);

    embed_kernel<<<Bsz * Nn, 256>>>(ents, rels, ent_table, rel_table, x, xb);
    adjpack_kernel<<<Bsz * Nn * 32 / 8, 256>>>(adjs, adjb);
    packqkv_i<<<dim3(384, 2), 256>>>(Wq, Wk, Wv, wqkvi);
    cvt_i<<<dim3(512, 2), 256>>>(l1w, w1i, 1024, 128 * 1024);
    cvt_i<<<dim3(512, 2), 256>>>(l2w, w2i, 256, 512 * 256);

    for (int j = 0; j < 2; j++) {
        const unsigned* wqkv = wqkvi + (size_t)j * 98304;
        const unsigned* w1   = w1i   + (size_t)j * 131072;
        const unsigned* w2   = w2i   + (size_t)j * 131072;
        const float* b1 = l1b + (size_t)j * 4 * Hd;
        const float* b2 = l2b + (size_t)j * Hd;
        const float* lg = ln_g + (size_t)j * Hd;
        const float* lb = ln_b + (size_t)j * Hd;
        const float* al = alpha + (size_t)j * 4 * Hd;

        gemm_tc<<<dim3(6, 128), 256>>>(xb, wqkv, nullptr, qkvb,
                                       Hd, Hd, 768, 768, nullptr, nullptr, 0);

        vpack_kernel<<<4096, 256>>>(qkvb, vp);

        flash_attn<<<dim3(8, Bsz * 4), 256, FL_SMEM>>>(qkvb, vp, adjb, x, o);

        ln_kernel<<<Mrows / 8, 256>>>(o, nullptr, lg, lb, tb, tbb);

        gemm_tc<<<dim3(8, 128), 256>>>(tbb, w1, nullptr, h1b,
                                       Hd, Hd, 4 * Hd, 4 * Hd, b1, al, 1);
        gemm_tc<<<dim3(2, 128), 256>>>(h1b, w2, h2, nullptr,
                                       4 * Hd, 4 * Hd, Hd, Hd, b2, nullptr, 2);

        if (j == 0)
            ln_kernel<<<Mrows / 8, 256>>>(h2, tb, lg, lb, x, xb);
        else
            ln_kernel<<<Mrows / 8, 256>>>(h2, tb, lg, lb, out, nullptr);
    }

    int tail = out_size - XSZ;
    if (tail > 0)
        fill_tail_kernel<<<(tail + 255) / 256, 256>>>(out, XSZ, out_size);
}